// round 9
// baseline (speedup 1.0000x reference)
#include <cuda_runtime.h>
#include <cuda_fp16.h>

#define NN 100000
#define NE 3200000
#define DF 128
#define H1 32
#define H2 16
#define NC 8
#define NBLK 391          // ceil(NN/256)

// ---- scratch (device globals; no allocs allowed) ----
__device__ __align__(16) __half2 g_g1h[NN * (H1 / 2)]; // g1 = (x@W1)*dinv, fp16
__device__ __align__(16) __half2 g_g2h[NN * (H2 / 2)]; // g2 = (relu1@W2)*dinv, fp16
__device__ __align__(16) float g_agg2[NN * H2];        // aggregated layer-2 (fp32)
__device__ float g_dinv[NN];
__device__ int   g_cnt[NN];                      // in-degree (no self loop)
__device__ int   g_off[NN + 1];                  // CSR offsets
__device__ int   g_cur[NN];                      // placement cursors
__device__ int   g_bsum[NBLK + 1];
__device__ int   g_bpref[NBLK + 1];
__device__ int   g_csr[NE];                      // src ids grouped by dst

// ---- K0: cnt = 0 ----
__global__ void k_init() {
    int i = blockIdx.x * blockDim.x + threadIdx.x;
    if (i < NN) g_cnt[i] = 0;
}

// ---- K1: degree histogram from dst column only ----
__global__ void k_deg(const int* __restrict__ ei) {
    int e = blockIdx.x * blockDim.x + threadIdx.x;
    if (e < NE) atomicAdd(&g_cnt[ei[NE + e]], 1);
}

// ---- K2: dinv = rsqrt(deg+1)  (+1 = self loop) ----
__global__ void k_dinv() {
    int i = blockIdx.x * blockDim.x + threadIdx.x;
    if (i < NN) g_dinv[i] = rsqrtf((float)(g_cnt[i] + 1));
}

// ---- K3a: per-block exclusive scan of cnt ----
__global__ void k_scan_block() {
    __shared__ int swarp[8];
    __shared__ int soff[8];
    int t = threadIdx.x;
    int i = blockIdx.x * 256 + t;
    int v = (i < NN) ? g_cnt[i] : 0;
    int incl = v;
#pragma unroll
    for (int d = 1; d < 32; d <<= 1) {
        int n = __shfl_up_sync(~0u, incl, d);
        if ((t & 31) >= d) incl += n;
    }
    if ((t & 31) == 31) swarp[t >> 5] = incl;
    __syncthreads();
    if (t == 0) {
        int run = 0;
#pragma unroll
        for (int w = 0; w < 8; w++) { soff[w] = run; run += swarp[w]; }
        g_bsum[blockIdx.x] = run;
    }
    __syncthreads();
    if (i < NN) g_off[i] = incl - v + soff[t >> 5];
}

// ---- K3b: scan the 391 block sums (one block) ----
__global__ void k_scan_top() {
    __shared__ int sv[512];
    int t = threadIdx.x;
    int v = (t < NBLK) ? g_bsum[t] : 0;
    sv[t] = v;
    __syncthreads();
    for (int d = 1; d < 512; d <<= 1) {
        int n = (t >= d) ? sv[t - d] : 0;
        __syncthreads();
        sv[t] += n;
        __syncthreads();
    }
    if (t < NBLK) g_bpref[t] = sv[t] - v;   // exclusive
}

// ---- K3c: add block prefixes; init cursors; off[NN]=NE ----
__global__ void k_scan_add() {
    int i = blockIdx.x * blockDim.x + threadIdx.x;
    if (i < NN) {
        int o = g_off[i] + g_bpref[i >> 8];
        g_off[i] = o;
        g_cur[i] = o;
    }
    if (i == 0) g_off[NN] = NE;
}

// ---- K4: place edges into CSR slots directly from input columns ----
__global__ void k_place(const int* __restrict__ ei) {
    int e = blockIdx.x * blockDim.x + threadIdx.x;
    if (e < NE) {
        int s = ei[e];
        int d = ei[NE + e];
        int pos = atomicAdd(&g_cur[d], 1);
        g_csr[pos] = s;
    }
}

// ---- K5: g1 = (x @ W1) * dinv  -> fp16 packed ----
__global__ void k_gemm1(const float* __restrict__ x, const float* __restrict__ W1) {
    __shared__ float sWt[H1][DF + 4];   // W1 transposed: [col][k]
    __shared__ float sx[32][DF + 4];    // 32 node rows per block
    int tid = threadIdx.x;
    for (int i = tid; i < DF * H1; i += 256) {
        int k = i >> 5, j = i & 31;
        sWt[j][k] = W1[i];
    }
    int node0 = blockIdx.x * 32;
    for (int i = tid; i < 32 * (DF / 4); i += 256) {
        int r = i >> 5, c = i & 31;
        ((float4*)&sx[r][0])[c] =
            ((const float4*)(x + (size_t)(node0 + r) * DF))[c];
    }
    __syncthreads();
    int warp = tid >> 5, lane = tid & 31;
    int nb = warp * 4;
    float acc0 = 0.f, acc1 = 0.f, acc2 = 0.f, acc3 = 0.f;
    const float4* wt = (const float4*)&sWt[lane][0];
    const float4* x0 = (const float4*)&sx[nb + 0][0];
    const float4* x1 = (const float4*)&sx[nb + 1][0];
    const float4* x2 = (const float4*)&sx[nb + 2][0];
    const float4* x3 = (const float4*)&sx[nb + 3][0];
#pragma unroll 8
    for (int q = 0; q < DF / 4; q++) {
        float4 w = wt[q];
        float4 a = x0[q], b = x1[q], c = x2[q], d = x3[q];
        acc0 += a.x * w.x + a.y * w.y + a.z * w.z + a.w * w.w;
        acc1 += b.x * w.x + b.y * w.y + b.z * w.z + b.w * w.w;
        acc2 += c.x * w.x + c.y * w.y + c.z * w.z + c.w * w.w;
        acc3 += d.x * w.x + d.y * w.y + d.z * w.z + d.w * w.w;
    }
    int n = node0 + nb;
    acc0 *= g_dinv[n + 0];
    acc1 *= g_dinv[n + 1];
    acc2 *= g_dinv[n + 2];
    acc3 *= g_dinv[n + 3];
    // pack adjacent feature columns into half2 (even lanes store)
    float o0 = __shfl_down_sync(~0u, acc0, 1);
    float o1 = __shfl_down_sync(~0u, acc1, 1);
    float o2 = __shfl_down_sync(~0u, acc2, 1);
    float o3 = __shfl_down_sync(~0u, acc3, 1);
    if ((lane & 1) == 0) {
        int h = lane >> 1;
        g_g1h[(n + 0) * (H1 / 2) + h] = __floats2half2_rn(acc0, o0);
        g_g1h[(n + 1) * (H1 / 2) + h] = __floats2half2_rn(acc1, o1);
        g_g1h[(n + 2) * (H1 / 2) + h] = __floats2half2_rn(acc2, o2);
        g_g1h[(n + 3) * (H1 / 2) + h] = __floats2half2_rn(acc3, o3);
    }
}

// ---- K6: gather layer-1 (fp16) + relu + W2 matvec + dinv -> g2 fp16 ----
// warp per node; half-warp per edge; lane handles feature pair fp
__global__ void k_gather_mid(const float* __restrict__ b1, const float* __restrict__ W2) {
    __shared__ float sW2[H1 * H2];
    __shared__ float su[8][H1 + 2];
    int tid = threadIdx.x;
    for (int i = tid; i < H1 * H2; i += 256) sW2[i] = W2[i];
    __syncthreads();
    int warp = tid >> 5, lane = tid & 31;
    int node = blockIdx.x * 8 + warp;       // NN % 8 == 0
    int sub = lane >> 4;                    // which edge of the pair
    int fp  = lane & 15;                    // feature-pair index
    int s = g_off[node], t = g_off[node + 1];
    float2 a0 = make_float2(0.f, 0.f), a1 = make_float2(0.f, 0.f);
    int e = s + sub;
    for (; e + 2 < t; e += 4) {
        int s0 = __ldg(&g_csr[e]);
        int s1 = __ldg(&g_csr[e + 2]);
        float2 v0 = __half22float2(g_g1h[s0 * (H1 / 2) + fp]);
        float2 v1 = __half22float2(g_g1h[s1 * (H1 / 2) + fp]);
        a0.x += v0.x; a0.y += v0.y;
        a1.x += v1.x; a1.y += v1.y;
    }
    for (; e < t; e += 2) {
        int s0 = __ldg(&g_csr[e]);
        float2 v0 = __half22float2(g_g1h[s0 * (H1 / 2) + fp]);
        a0.x += v0.x; a0.y += v0.y;
    }
    float ax = a0.x + a1.x, ay = a0.y + a1.y;
    // combine the two half-warps
    ax += __shfl_xor_sync(~0u, ax, 16);
    ay += __shfl_xor_sync(~0u, ay, 16);
    // self-loop + relu + bias (all lanes compute; halves duplicate)
    float2 sl = __half22float2(g_g1h[node * (H1 / 2) + fp]);
    float dinv = g_dinv[node];
    float ux = fmaxf(fmaf(ax + sl.x, dinv, __ldg(&b1[2 * fp])), 0.f);
    float uy = fmaxf(fmaf(ay + sl.y, dinv, __ldg(&b1[2 * fp + 1])), 0.f);
    if (sub == 0) {
        su[warp][2 * fp]     = ux;
        su[warp][2 * fp + 1] = uy;
    }
    __syncwarp();
    // matvec: output col = lane & 15 (lanes >=16 duplicate harmlessly)
    int col = lane & 15;
    float acc = 0.f;
#pragma unroll
    for (int k = 0; k < H1; k++)
        acc = fmaf(su[warp][k], sW2[k * H2 + col], acc);
    acc *= dinv;
    float nb = __shfl_down_sync(~0u, acc, 1);
    if (lane < 16 && (lane & 1) == 0)
        g_g2h[node * (H2 / 2) + (lane >> 1)] = __floats2half2_rn(acc, nb);
}

// ---- K7: gather layer-2 (fp16) -> agg2 fp32 (quarter-warp per edge) ----
__global__ void k_gather2() {
    int tid = threadIdx.x;
    int warp = tid >> 5, lane = tid & 31;
    int node = blockIdx.x * 8 + warp;
    int sub = lane >> 3;                    // 0..3
    int fp  = lane & 7;                     // feature-pair index
    int s = g_off[node], t = g_off[node + 1];
    float2 a0 = make_float2(0.f, 0.f), a1 = make_float2(0.f, 0.f);
    int e = s + sub;
    for (; e + 4 < t; e += 8) {
        int s0 = __ldg(&g_csr[e]);
        int s1 = __ldg(&g_csr[e + 4]);
        float2 v0 = __half22float2(g_g2h[s0 * (H2 / 2) + fp]);
        float2 v1 = __half22float2(g_g2h[s1 * (H2 / 2) + fp]);
        a0.x += v0.x; a0.y += v0.y;
        a1.x += v1.x; a1.y += v1.y;
    }
    for (; e < t; e += 4) {
        int s0 = __ldg(&g_csr[e]);
        float2 v0 = __half22float2(g_g2h[s0 * (H2 / 2) + fp]);
        a0.x += v0.x; a0.y += v0.y;
    }
    float ax = a0.x + a1.x, ay = a0.y + a1.y;
    ax += __shfl_xor_sync(~0u, ax, 8);
    ay += __shfl_xor_sync(~0u, ay, 8);
    ax += __shfl_xor_sync(~0u, ax, 16);
    ay += __shfl_xor_sync(~0u, ay, 16);
    if (sub == 0) {
        float2 sl = __half22float2(g_g2h[node * (H2 / 2) + fp]);
        ((float2*)g_agg2)[node * (H2 / 2) + fp] =
            make_float2(ax + sl.x, ay + sl.y);
    }
}

// ---- K8: relu(dinv*agg2 + b2) @ Wc + bc -> log_softmax -> out ----
__global__ void k_final(const float* __restrict__ b2, const float* __restrict__ Wc,
                        const float* __restrict__ bc, float* __restrict__ out) {
    int node = blockIdx.x * blockDim.x + threadIdx.x;
    if (node >= NN) return;
    float dinv = g_dinv[node];
    float u[H2];
    const float4* a = (const float4*)(g_agg2 + (size_t)node * H2);
#pragma unroll
    for (int q = 0; q < 4; q++) {
        float4 v = a[q];
        u[4 * q + 0] = v.x; u[4 * q + 1] = v.y;
        u[4 * q + 2] = v.z; u[4 * q + 3] = v.w;
    }
#pragma unroll
    for (int k = 0; k < H2; k++)
        u[k] = fmaxf(fmaf(u[k], dinv, __ldg(&b2[k])), 0.f);
    float l[NC];
#pragma unroll
    for (int j = 0; j < NC; j++) l[j] = __ldg(&bc[j]);
#pragma unroll
    for (int k = 0; k < H2; k++) {
        float uk = u[k];
#pragma unroll
        for (int j = 0; j < NC; j++)
            l[j] = fmaf(uk, __ldg(&Wc[k * NC + j]), l[j]);
    }
    float m = l[0];
#pragma unroll
    for (int j = 1; j < NC; j++) m = fmaxf(m, l[j]);
    float sum = 0.f;
#pragma unroll
    for (int j = 0; j < NC; j++) sum += expf(l[j] - m);
    float lse = m + logf(sum);
    float4* o = (float4*)(out + (size_t)node * NC);
    o[0] = make_float4(l[0] - lse, l[1] - lse, l[2] - lse, l[3] - lse);
    o[1] = make_float4(l[4] - lse, l[5] - lse, l[6] - lse, l[7] - lse);
}

extern "C" void kernel_launch(void* const* d_in, const int* in_sizes, int n_in,
                              void* d_out, int out_size) {
    (void)out_size;
    const float* x  = nullptr; const int* ei = nullptr;
    const float* W1 = nullptr; const float* b1 = nullptr;
    const float* W2 = nullptr; const float* b2 = nullptr;
    const float* Wc = nullptr; const float* bc = nullptr;
    for (int i = 0; i < n_in; i++) {
        switch (in_sizes[i]) {
            case NN * DF:    x  = (const float*)d_in[i]; break;  // 12,800,000
            case 2 * NE:     ei = (const int*)d_in[i];   break;  //  6,400,000
            case DF * H1:    W1 = (const float*)d_in[i]; break;  //      4,096
            case H1 * H2:    W2 = (const float*)d_in[i]; break;  //        512
            case H2 * NC:    Wc = (const float*)d_in[i]; break;  //        128
            case H1:         b1 = (const float*)d_in[i]; break;  //         32
            case H2:         b2 = (const float*)d_in[i]; break;  //         16
            case NC:         bc = (const float*)d_in[i]; break;  //          8
            default: break;
        }
    }
    float* out = (float*)d_out;

    k_init<<<NBLK, 256>>>();
    k_deg<<<NE / 256, 256>>>(ei);
    k_dinv<<<NBLK, 256>>>();
    k_scan_block<<<NBLK, 256>>>();
    k_scan_top<<<1, 512>>>();
    k_scan_add<<<NBLK, 256>>>();
    k_place<<<NE / 256, 256>>>(ei);
    k_gemm1<<<NN / 32, 256>>>(x, W1);       // 3125 blocks
    k_gather_mid<<<NN / 8, 256>>>(b1, W2);  // 12500 blocks
    k_gather2<<<NN / 8, 256>>>();
    k_final<<<NBLK, 256>>>(b2, Wc, bc, out);
}

// round 10
// speedup vs baseline: 1.0003x; 1.0003x over previous
#include <cuda_runtime.h>
#include <cuda_fp16.h>

#define NN 100000
#define NE 3200000
#define DF 128
#define H1 32
#define H2 16
#define NC 8
#define NBLK 391          // ceil(NN/256)

// ---- scratch (device globals; no allocs allowed) ----
__device__ __align__(16) __half2 g_g1h[NN * (H1 / 2)]; // g1 fp16 (row = 64 B)
__device__ __align__(16) __half2 g_g2h[NN * (H2 / 2)]; // g2 fp16 (row = 32 B)
__device__ __align__(16) float g_agg2[NN * H2];        // layer-2 aggregate fp32
__device__ float g_dinv[NN];
__device__ int   g_cnt[NN];
__device__ int   g_off[NN + 1];
__device__ int   g_cur[NN];
__device__ int   g_bsum[NBLK + 1];
__device__ int   g_bpref[NBLK + 1];
__device__ int   g_csr[NE];

// ---- K0: cnt = 0 ----
__global__ void k_init() {
    int i = blockIdx.x * blockDim.x + threadIdx.x;
    if (i < NN) g_cnt[i] = 0;
}

// ---- K1: degree histogram, int4-vectorized (4 edges/thread) ----
__global__ void k_deg(const int* __restrict__ ei) {
    int i = blockIdx.x * blockDim.x + threadIdx.x;   // 0 .. NE/4-1
    int4 d = __ldg((const int4*)(ei + NE) + i);
    atomicAdd(&g_cnt[d.x], 1);
    atomicAdd(&g_cnt[d.y], 1);
    atomicAdd(&g_cnt[d.z], 1);
    atomicAdd(&g_cnt[d.w], 1);
}

// ---- K2: per-block exclusive scan of cnt (+ dinv fused) ----
__global__ void k_scan_block() {
    __shared__ int swarp[8];
    __shared__ int soff[8];
    int t = threadIdx.x;
    int i = blockIdx.x * 256 + t;
    int v = (i < NN) ? g_cnt[i] : 0;
    if (i < NN) g_dinv[i] = rsqrtf((float)(v + 1));   // self loop included
    int incl = v;
#pragma unroll
    for (int d = 1; d < 32; d <<= 1) {
        int n = __shfl_up_sync(~0u, incl, d);
        if ((t & 31) >= d) incl += n;
    }
    if ((t & 31) == 31) swarp[t >> 5] = incl;
    __syncthreads();
    if (t == 0) {
        int run = 0;
#pragma unroll
        for (int w = 0; w < 8; w++) { soff[w] = run; run += swarp[w]; }
        g_bsum[blockIdx.x] = run;
    }
    __syncthreads();
    if (i < NN) g_off[i] = incl - v + soff[t >> 5];
}

// ---- K3: scan the 391 block sums (one block) ----
__global__ void k_scan_top() {
    __shared__ int sv[512];
    int t = threadIdx.x;
    int v = (t < NBLK) ? g_bsum[t] : 0;
    sv[t] = v;
    __syncthreads();
    for (int d = 1; d < 512; d <<= 1) {
        int n = (t >= d) ? sv[t - d] : 0;
        __syncthreads();
        sv[t] += n;
        __syncthreads();
    }
    if (t < NBLK) g_bpref[t] = sv[t] - v;   // exclusive
}

// ---- K4: add block prefixes; init cursors; off[NN]=NE ----
__global__ void k_scan_add() {
    int i = blockIdx.x * blockDim.x + threadIdx.x;
    if (i < NN) {
        int o = g_off[i] + g_bpref[i >> 8];
        g_off[i] = o;
        g_cur[i] = o;
    }
    if (i == 0) g_off[NN] = NE;
}

// ---- K5: place edges into CSR slots, int4-vectorized ----
__global__ void k_place(const int* __restrict__ ei) {
    int i = blockIdx.x * blockDim.x + threadIdx.x;   // 0 .. NE/4-1
    int4 s = __ldg((const int4*)ei + i);
    int4 d = __ldg((const int4*)(ei + NE) + i);
    int p;
    p = atomicAdd(&g_cur[d.x], 1); g_csr[p] = s.x;
    p = atomicAdd(&g_cur[d.y], 1); g_csr[p] = s.y;
    p = atomicAdd(&g_cur[d.z], 1); g_csr[p] = s.z;
    p = atomicAdd(&g_cur[d.w], 1); g_csr[p] = s.w;
}

// ---- K6: g1 = (x @ W1) * dinv  -> fp16 packed ----
__global__ void k_gemm1(const float* __restrict__ x, const float* __restrict__ W1) {
    __shared__ float sWt[H1][DF + 4];
    __shared__ float sx[32][DF + 4];
    int tid = threadIdx.x;
    for (int i = tid; i < DF * H1; i += 256) {
        int k = i >> 5, j = i & 31;
        sWt[j][k] = W1[i];
    }
    int node0 = blockIdx.x * 32;
    for (int i = tid; i < 32 * (DF / 4); i += 256) {
        int r = i >> 5, c = i & 31;
        ((float4*)&sx[r][0])[c] =
            ((const float4*)(x + (size_t)(node0 + r) * DF))[c];
    }
    __syncthreads();
    int warp = tid >> 5, lane = tid & 31;
    int nb = warp * 4;
    float acc0 = 0.f, acc1 = 0.f, acc2 = 0.f, acc3 = 0.f;
    const float4* wt = (const float4*)&sWt[lane][0];
    const float4* x0 = (const float4*)&sx[nb + 0][0];
    const float4* x1 = (const float4*)&sx[nb + 1][0];
    const float4* x2 = (const float4*)&sx[nb + 2][0];
    const float4* x3 = (const float4*)&sx[nb + 3][0];
#pragma unroll 8
    for (int q = 0; q < DF / 4; q++) {
        float4 w = wt[q];
        float4 a = x0[q], b = x1[q], c = x2[q], d = x3[q];
        acc0 += a.x * w.x + a.y * w.y + a.z * w.z + a.w * w.w;
        acc1 += b.x * w.x + b.y * w.y + b.z * w.z + b.w * w.w;
        acc2 += c.x * w.x + c.y * w.y + c.z * w.z + c.w * w.w;
        acc3 += d.x * w.x + d.y * w.y + d.z * w.z + d.w * w.w;
    }
    int n = node0 + nb;
    acc0 *= g_dinv[n + 0];
    acc1 *= g_dinv[n + 1];
    acc2 *= g_dinv[n + 2];
    acc3 *= g_dinv[n + 3];
    float o0 = __shfl_down_sync(~0u, acc0, 1);
    float o1 = __shfl_down_sync(~0u, acc1, 1);
    float o2 = __shfl_down_sync(~0u, acc2, 1);
    float o3 = __shfl_down_sync(~0u, acc3, 1);
    if ((lane & 1) == 0) {
        int h = lane >> 1;
        g_g1h[(n + 0) * (H1 / 2) + h] = __floats2half2_rn(acc0, o0);
        g_g1h[(n + 1) * (H1 / 2) + h] = __floats2half2_rn(acc1, o1);
        g_g1h[(n + 2) * (H1 / 2) + h] = __floats2half2_rn(acc2, o2);
        g_g1h[(n + 3) * (H1 / 2) + h] = __floats2half2_rn(acc3, o3);
    }
}

__device__ __forceinline__ void acc8(float* a, uint4 v) {
    float2 f0 = __half22float2(*(__half2*)&v.x);
    float2 f1 = __half22float2(*(__half2*)&v.y);
    float2 f2 = __half22float2(*(__half2*)&v.z);
    float2 f3 = __half22float2(*(__half2*)&v.w);
    a[0] += f0.x; a[1] += f0.y; a[2] += f1.x; a[3] += f1.y;
    a[4] += f2.x; a[5] += f2.y; a[6] += f3.x; a[7] += f3.y;
}

// ---- K7: gather layer-1 + relu + W2 matvec -> g2 fp16 ----
// warp/node; slot=lane>>2 (8 edges in flight), q=lane&3 (8 feats, 16 B)
__global__ void k_gather_mid(const float* __restrict__ b1, const float* __restrict__ W2) {
    __shared__ float sW2[H1 * H2];
    __shared__ float su[8][H1 + 4];
    int tid = threadIdx.x;
    for (int i = tid; i < H1 * H2; i += 256) sW2[i] = W2[i];
    __syncthreads();
    int warp = tid >> 5, lane = tid & 31;
    int node = blockIdx.x * 8 + warp;       // NN % 8 == 0
    int slot = lane >> 2, q = lane & 3;
    int s = g_off[node], t = g_off[node + 1];
    float a[8] = {0.f, 0.f, 0.f, 0.f, 0.f, 0.f, 0.f, 0.f};
    int e = s + slot;
    for (; e + 8 < t; e += 16) {            // 2 rows in flight per lane
        int s0 = __ldg(&g_csr[e]);
        int s1 = __ldg(&g_csr[e + 8]);
        uint4 v0 = __ldg((const uint4*)(g_g1h + s0 * (H1 / 2)) + q);
        uint4 v1 = __ldg((const uint4*)(g_g1h + s1 * (H1 / 2)) + q);
        acc8(a, v0);
        acc8(a, v1);
    }
    if (e < t) {
        int s0 = __ldg(&g_csr[e]);
        uint4 v0 = __ldg((const uint4*)(g_g1h + s0 * (H1 / 2)) + q);
        acc8(a, v0);
    }
    // reduce across 8 slots
#pragma unroll
    for (int m = 4; m < 32; m <<= 1)
#pragma unroll
        for (int i = 0; i < 8; i++)
            a[i] += __shfl_xor_sync(~0u, a[i], m);
    // self loop + relu + bias
    uint4 sv = *((const uint4*)(g_g1h + node * (H1 / 2)) + q);
    float sl[8] = {0.f, 0.f, 0.f, 0.f, 0.f, 0.f, 0.f, 0.f};
    acc8(sl, sv);
    float dinv = g_dinv[node];
    if (slot == 0) {
        float u[8];
#pragma unroll
        for (int i = 0; i < 8; i++)
            u[i] = fmaxf(fmaf(a[i] + sl[i], dinv, __ldg(&b1[8 * q + i])), 0.f);
        ((float4*)&su[warp][8 * q])[0] = make_float4(u[0], u[1], u[2], u[3]);
        ((float4*)&su[warp][8 * q])[1] = make_float4(u[4], u[5], u[6], u[7]);
    }
    __syncwarp();
    // matvec: col = lane & 15 (upper half duplicates harmlessly)
    int col = lane & 15;
    float acc = 0.f;
#pragma unroll
    for (int k = 0; k < H1; k++)
        acc = fmaf(su[warp][k], sW2[k * H2 + col], acc);
    acc *= dinv;
    float nb = __shfl_down_sync(~0u, acc, 1);
    if (lane < 16 && (lane & 1) == 0)
        g_g2h[node * (H2 / 2) + (lane >> 1)] = __floats2half2_rn(acc, nb);
}

__device__ __forceinline__ void acc4(float* a, uint2 v) {
    float2 f0 = __half22float2(*(__half2*)&v.x);
    float2 f1 = __half22float2(*(__half2*)&v.y);
    a[0] += f0.x; a[1] += f0.y; a[2] += f1.x; a[3] += f1.y;
}

// ---- K8: gather layer-2 -> agg2 fp32 ----
// warp/node; slot=lane>>2 (8 edges), q=lane&3 (4 feats, 8 B)
__global__ void k_gather2() {
    int tid = threadIdx.x;
    int warp = tid >> 5, lane = tid & 31;
    int node = blockIdx.x * 8 + warp;
    int slot = lane >> 2, q = lane & 3;
    int s = g_off[node], t = g_off[node + 1];
    float a[4] = {0.f, 0.f, 0.f, 0.f};
    int e = s + slot;
    for (; e + 8 < t; e += 16) {
        int s0 = __ldg(&g_csr[e]);
        int s1 = __ldg(&g_csr[e + 8]);
        uint2 v0 = __ldg((const uint2*)(g_g2h + s0 * (H2 / 2)) + q);
        uint2 v1 = __ldg((const uint2*)(g_g2h + s1 * (H2 / 2)) + q);
        acc4(a, v0);
        acc4(a, v1);
    }
    if (e < t) {
        int s0 = __ldg(&g_csr[e]);
        uint2 v0 = __ldg((const uint2*)(g_g2h + s0 * (H2 / 2)) + q);
        acc4(a, v0);
    }
#pragma unroll
    for (int m = 4; m < 32; m <<= 1)
#pragma unroll
        for (int i = 0; i < 4; i++)
            a[i] += __shfl_xor_sync(~0u, a[i], m);
    if (slot == 0) {
        uint2 sv = *((const uint2*)(g_g2h + node * (H2 / 2)) + q);
        acc4(a, sv);   // self loop
        ((float4*)(g_agg2 + node * H2))[q] = make_float4(a[0], a[1], a[2], a[3]);
    }
}

// ---- K9: relu(dinv*agg2 + b2) @ Wc + bc -> log_softmax -> out ----
__global__ void k_final(const float* __restrict__ b2, const float* __restrict__ Wc,
                        const float* __restrict__ bc, float* __restrict__ out) {
    int node = blockIdx.x * blockDim.x + threadIdx.x;
    if (node >= NN) return;
    float dinv = g_dinv[node];
    float u[H2];
    const float4* a = (const float4*)(g_agg2 + (size_t)node * H2);
#pragma unroll
    for (int q = 0; q < 4; q++) {
        float4 v = a[q];
        u[4 * q + 0] = v.x; u[4 * q + 1] = v.y;
        u[4 * q + 2] = v.z; u[4 * q + 3] = v.w;
    }
#pragma unroll
    for (int k = 0; k < H2; k++)
        u[k] = fmaxf(fmaf(u[k], dinv, __ldg(&b2[k])), 0.f);
    float l[NC];
#pragma unroll
    for (int j = 0; j < NC; j++) l[j] = __ldg(&bc[j]);
#pragma unroll
    for (int k = 0; k < H2; k++) {
        float uk = u[k];
#pragma unroll
        for (int j = 0; j < NC; j++)
            l[j] = fmaf(uk, __ldg(&Wc[k * NC + j]), l[j]);
    }
    float m = l[0];
#pragma unroll
    for (int j = 1; j < NC; j++) m = fmaxf(m, l[j]);
    float sum = 0.f;
#pragma unroll
    for (int j = 0; j < NC; j++) sum += expf(l[j] - m);
    float lse = m + logf(sum);
    float4* o = (float4*)(out + (size_t)node * NC);
    o[0] = make_float4(l[0] - lse, l[1] - lse, l[2] - lse, l[3] - lse);
    o[1] = make_float4(l[4] - lse, l[5] - lse, l[6] - lse, l[7] - lse);
}

extern "C" void kernel_launch(void* const* d_in, const int* in_sizes, int n_in,
                              void* d_out, int out_size) {
    (void)out_size;
    const float* x  = nullptr; const int* ei = nullptr;
    const float* W1 = nullptr; const float* b1 = nullptr;
    const float* W2 = nullptr; const float* b2 = nullptr;
    const float* Wc = nullptr; const float* bc = nullptr;
    for (int i = 0; i < n_in; i++) {
        switch (in_sizes[i]) {
            case NN * DF:    x  = (const float*)d_in[i]; break;
            case 2 * NE:     ei = (const int*)d_in[i];   break;
            case DF * H1:    W1 = (const float*)d_in[i]; break;
            case H1 * H2:    W2 = (const float*)d_in[i]; break;
            case H2 * NC:    Wc = (const float*)d_in[i]; break;
            case H1:         b1 = (const float*)d_in[i]; break;
            case H2:         b2 = (const float*)d_in[i]; break;
            case NC:         bc = (const float*)d_in[i]; break;
            default: break;
        }
    }
    float* out = (float*)d_out;

    k_init<<<NBLK, 256>>>();
    k_deg<<<NE / 4 / 256, 256>>>(ei);         // 3125 blocks
    k_scan_block<<<NBLK, 256>>>();            // dinv fused
    k_scan_top<<<1, 512>>>();
    k_scan_add<<<NBLK, 256>>>();
    k_place<<<NE / 4 / 256, 256>>>(ei);       // 3125 blocks
    k_gemm1<<<NN / 32, 256>>>(x, W1);         // 3125 blocks
    k_gather_mid<<<NN / 8, 256>>>(b1, W2);    // 12500 blocks
    k_gather2<<<NN / 8, 256>>>();
    k_final<<<NBLK, 256>>>(b2, Wc, bc, out);
}